// round 1
// baseline (speedup 1.0000x reference)
#include <cuda_runtime.h>
#include <cuda_bf16.h>
#include <math.h>

#define S_LEN 2048
#define DIM 1024
#define NH 16
#define KVH 4
#define HD 64
#define KVDIM 256
#define NTOT 1792   // 1024 (q) + 256 (k) + 256 (v) + 256 (g)

// ---------------- device scratch (no allocations allowed) ----------------
__device__ float g_qkvg[S_LEN * NTOT];       // [S, 1792]
__device__ float g_q[NH * S_LEN * HD];       // [H][S][64] post norm/rotary/gain
__device__ float g_k[KVH * S_LEN * HD];      // [KVH][S][64]
__device__ float g_v[KVH * S_LEN * HD];      // gated V
__device__ float g_a[NH * S_LEN * HD];       // attention out: half0 in d<32, half1 in d>=32
__device__ float g_y[S_LEN * DIM];           // combined, token-major

// ---------------- SGEMM: C[M,N] = A[M,K] @ B[N,K]^T ----------------------
// B is a virtual concatenation of up to 4 row-major [n_i, K] matrices.
// 128x128 block tile, BK=8, 256 threads, 8x8 register microtile,
// register prefetch of the next K-slab to hide global latency.
__global__ __launch_bounds__(256) void sgemm_abt(
    const float* __restrict__ A,
    float* __restrict__ C, int ldc, int K,
    const float* __restrict__ B0, const float* __restrict__ B1,
    const float* __restrict__ B2, const float* __restrict__ B3,
    int n0, int n1, int n2)
{
    __shared__ float As[8][128];
    __shared__ float Bs[8][128];

    const int m0 = blockIdx.y * 128;
    const int nb = blockIdx.x * 128;
    const int t  = threadIdx.x;
    const int lr = t >> 1;            // 0..127: row within tile for loading
    const int lk = (t & 1) << 2;      // 0 or 4: k sub-offset
    const int ty = t >> 4;            // 0..15
    const int tx = t & 15;            // 0..15

    // resolve virtual B row pointer
    const int n = nb + lr;
    const float* brp;
    if      (n < n0) brp = B0 + (size_t)n        * K;
    else if (n < n1) brp = B1 + (size_t)(n - n0) * K;
    else if (n < n2) brp = B2 + (size_t)(n - n1) * K;
    else             brp = B3 + (size_t)(n - n2) * K;

    const float* arp = A + (size_t)(m0 + lr) * K;

    float4 aReg = *(const float4*)(arp + lk);
    float4 bReg = *(const float4*)(brp + lk);

    float acc[8][8];
    #pragma unroll
    for (int i = 0; i < 8; i++)
        #pragma unroll
        for (int j = 0; j < 8; j++) acc[i][j] = 0.0f;

    for (int k0 = 0; k0 < K; k0 += 8) {
        As[lk + 0][lr] = aReg.x; As[lk + 1][lr] = aReg.y;
        As[lk + 2][lr] = aReg.z; As[lk + 3][lr] = aReg.w;
        Bs[lk + 0][lr] = bReg.x; Bs[lk + 1][lr] = bReg.y;
        Bs[lk + 2][lr] = bReg.z; Bs[lk + 3][lr] = bReg.w;
        __syncthreads();

        const int kn = k0 + 8;
        if (kn < K) {
            aReg = *(const float4*)(arp + kn + lk);
            bReg = *(const float4*)(brp + kn + lk);
        }

        #pragma unroll
        for (int kk = 0; kk < 8; kk++) {
            float ar[8], br[8];
            *(float4*)&ar[0] = *(const float4*)&As[kk][ty * 8];
            *(float4*)&ar[4] = *(const float4*)&As[kk][ty * 8 + 4];
            *(float4*)&br[0] = *(const float4*)&Bs[kk][tx * 8];
            *(float4*)&br[4] = *(const float4*)&Bs[kk][tx * 8 + 4];
            #pragma unroll
            for (int i = 0; i < 8; i++)
                #pragma unroll
                for (int j = 0; j < 8; j++)
                    acc[i][j] += ar[i] * br[j];
        }
        __syncthreads();
    }

    #pragma unroll
    for (int i = 0; i < 8; i++) {
        float* crow = C + (size_t)(m0 + ty * 8 + i) * ldc + nb + tx * 8;
        ((float4*)crow)[0] = make_float4(acc[i][0], acc[i][1], acc[i][2], acc[i][3]);
        ((float4*)crow)[1] = make_float4(acc[i][4], acc[i][5], acc[i][6], acc[i][7]);
    }
}

// ---------------- postprocess: V-gate, RMS-norm, rotary, q_gain ----------
// grid (S, 21), block 64. unit<16: q head; unit<20: k head; unit==20: v gate.
__global__ __launch_bounds__(64) void postproc(const float* __restrict__ q_gain)
{
    const int m    = blockIdx.x;
    const int unit = blockIdx.y;
    const int t    = threadIdx.x;
    const float* row = g_qkvg + (size_t)m * NTOT;

    if (unit == 20) {
        #pragma unroll
        for (int i = t; i < KVDIM; i += 64) {
            float v = row[1280 + i];
            float g = row[1536 + i];
            float vg = v / (1.0f + expf(-g));
            g_v[(size_t)(i >> 6) * (S_LEN * HD) + (size_t)m * HD + (i & 63)] = vg;
        }
        return;
    }

    const bool isq = unit < 16;
    const int h    = isq ? unit : unit - 16;
    const int col0 = isq ? h * HD : 1024 + h * HD;

    float x = row[col0 + t];

    // mean(x^2) over the 64-wide head
    float ss = x * x;
    #pragma unroll
    for (int o = 16; o > 0; o >>= 1) ss += __shfl_xor_sync(0xffffffffu, ss, o);
    __shared__ float s2[2];
    __shared__ float xs[64];
    if ((t & 31) == 0) s2[t >> 5] = ss;
    __syncthreads();
    const float tot = s2[0] + s2[1];
    const float xn  = x * rsqrtf(tot * (1.0f / 64.0f) + 1.1920929e-7f); // fp32 eps
    xs[t] = xn;
    __syncthreads();

    const float gain = isq ? q_gain[h] : 1.0f;
    float* dst = (isq ? g_q + (size_t)h * (S_LEN * HD)
                      : g_k + (size_t)h * (S_LEN * HD)) + (size_t)m * HD;

    if (t < 32) {
        const float x1 = xs[t], x2 = xs[t + 32];
        // match reference fp32 rounding: angle = ((2t)/64) * pi_f ; ang = m * angle
        const float angle = ((float)(2 * t) / 64.0f) * 3.14159274101257324f;
        const float ang   = (float)m * angle;
        // accurate range reduction in double, then fp32 trig on small arg
        double a = (double)ang;
        double kq = rint(a * 0.15915494309189535);     // a / (2*pi)
        a -= kq * 6.283185307179586;
        float c, sn;
        sincosf((float)a, &sn, &c);
        const float radius = 1.0f / (1.0f + (float)m * 0.01f);
        c *= radius; sn *= radius;
        dst[t]      = ( x1 * c + x2 * sn) * gain;
        dst[t + 32] = (-x1 * sn + x2 * c) * gain;
    }
}

// ---------------- flash attention, fp32, per-half (d=32) -----------------
// grid (32 q-tiles, 16 heads, 2 halves), block 64: one thread per query row.
__global__ __launch_bounds__(64) void attn_kernel()
{
    const int qt   = gridDim.x - 1 - blockIdx.x;  // big tiles first (tail balance)
    const int h    = blockIdx.y;
    const int half = blockIdx.z;
    const int kvh  = h >> 2;
    const int t    = threadIdx.x;
    const int qrow = qt * 64 + t;

    const float SCALE = 0.17677669529663688f;     // 1/sqrt(32)

    const float* qptr = g_q + ((size_t)h * S_LEN + qrow) * HD + half * 32;
    float q[32];
    #pragma unroll
    for (int i = 0; i < 8; i++) {
        float4 v4 = ((const float4*)qptr)[i];
        q[4*i] = v4.x; q[4*i+1] = v4.y; q[4*i+2] = v4.z; q[4*i+3] = v4.w;
    }

    float acc[32];
    #pragma unroll
    for (int d = 0; d < 32; d++) acc[d] = 0.0f;
    float mrun = -INFINITY, lrun = 0.0f;

    __shared__ float ks[32][36];
    __shared__ float vs[32][36];

    const float* kbase = g_k + (size_t)kvh * S_LEN * HD + half * 32;
    const float* vbase = g_v + (size_t)kvh * S_LEN * HD + half * 32;

    const int lr = t >> 1;            // 0..31: key row to load
    const int lc = (t & 1) << 4;      // 0 or 16

    const int ntiles = 2 * qt + 2;    // keys 0 .. qt*64+63
    for (int kt = 0; kt < ntiles; kt++) {
        const float* krow = kbase + (size_t)(kt * 32 + lr) * HD + lc;
        const float* vrow = vbase + (size_t)(kt * 32 + lr) * HD + lc;
        #pragma unroll
        for (int i = 0; i < 4; i++) {
            *(float4*)&ks[lr][lc + 4*i] = *(const float4*)(krow + 4*i);
            *(float4*)&vs[lr][lc + 4*i] = *(const float4*)(vrow + 4*i);
        }
        __syncthreads();

        float sc[32];
        #pragma unroll
        for (int j = 0; j < 32; j++) {
            float s = 0.0f;
            #pragma unroll
            for (int dv = 0; dv < 8; dv++) {
                float4 kv = *(const float4*)&ks[j][4*dv];  // broadcast LDS
                s += q[4*dv]   * kv.x;
                s += q[4*dv+1] * kv.y;
                s += q[4*dv+2] * kv.z;
                s += q[4*dv+3] * kv.w;
            }
            sc[j] = (kt * 32 + j > qrow) ? -INFINITY : s * SCALE;
        }

        float mt = sc[0];
        #pragma unroll
        for (int j = 1; j < 32; j++) mt = fmaxf(mt, sc[j]);
        const float mnew = fmaxf(mrun, mt);
        const float corr = expf(mrun - mnew);
        lrun *= corr;
        #pragma unroll
        for (int d = 0; d < 32; d++) acc[d] *= corr;

        #pragma unroll
        for (int j = 0; j < 32; j++) {
            const float p = expf(sc[j] - mnew);
            lrun += p;
            #pragma unroll
            for (int dv = 0; dv < 8; dv++) {
                float4 vv = *(const float4*)&vs[j][4*dv];  // broadcast LDS
                acc[4*dv]   += p * vv.x;
                acc[4*dv+1] += p * vv.y;
                acc[4*dv+2] += p * vv.z;
                acc[4*dv+3] += p * vv.w;
            }
        }
        mrun = mnew;
        __syncthreads();
    }

    const float inv = 1.0f / lrun;
    float* optr = g_a + ((size_t)h * S_LEN + qrow) * HD + half * 32;
    #pragma unroll
    for (int i = 0; i < 8; i++) {
        ((float4*)optr)[i] = make_float4(acc[4*i] * inv, acc[4*i+1] * inv,
                                         acc[4*i+2] * inv, acc[4*i+3] * inv);
    }
}

// ---------------- differential combine: y = [a1 - l*a2, a1 + l*a2] -------
__global__ __launch_bounds__(512) void combine(const float* __restrict__ lambda_p)
{
    const int m = blockIdx.x;
    const int t = threadIdx.x;        // 512: h = t/32, j = t%32
    const int h = t >> 5, j = t & 31;
    const float lam = lambda_p[h];
    const float* ap = g_a + ((size_t)h * S_LEN + m) * HD;
    const float a1 = ap[j], a2 = ap[j + 32];
    float* yr = g_y + (size_t)m * DIM + h * HD;
    yr[j]      = a1 - lam * a2;
    yr[j + 32] = a1 + lam * a2;
}

// ---------------- launch ---------------------------------------------------
extern "C" void kernel_launch(void* const* d_in, const int* in_sizes, int n_in,
                              void* d_out, int out_size)
{
    const float* x        = (const float*)d_in[0];
    const float* Wq       = (const float*)d_in[1];
    const float* Wk       = (const float*)d_in[2];
    const float* Wv       = (const float*)d_in[3];
    const float* Wg       = (const float*)d_in[4];
    const float* Wo       = (const float*)d_in[5];
    const float* q_gain   = (const float*)d_in[6];
    const float* lambda_p = (const float*)d_in[7];
    float* out = (float*)d_out;

    float *qkvg_p, *y_p;
    cudaGetSymbolAddress((void**)&qkvg_p, g_qkvg);
    cudaGetSymbolAddress((void**)&y_p, g_y);

    // 1) fused QKVG projection: [2048,1792] = x @ [Wq;Wk;Wv;Wg]^T
    dim3 g1(NTOT / 128, S_LEN / 128);
    sgemm_abt<<<g1, 256>>>(x, qkvg_p, NTOT, DIM,
                           Wq, Wk, Wv, Wg, 1024, 1280, 1536);

    // 2) gate V, RMS-norm + rotary + gain for Q/K
    postproc<<<dim3(S_LEN, 21), 64>>>(q_gain);

    // 3) split-half causal flash attention
    attn_kernel<<<dim3(S_LEN / 64, NH, 2), 64>>>();

    // 4) differential combine
    combine<<<S_LEN, 512>>>(lambda_p);

    // 5) output projection
    dim3 g2(DIM / 128, S_LEN / 128);
    sgemm_abt<<<g2, 256>>>(y_p, out, DIM, DIM,
                           Wo, Wo, Wo, Wo, DIM, DIM, DIM);
}